// round 13
// baseline (speedup 1.0000x reference)
#include <cuda_runtime.h>
#include <cstdint>

// SSIM loss: fused separable 11x11 Gaussian, warp-specialized producer/consumer.
// Producers (warps 0-4): vertical blur gmem->smem. Consumers (warps 5-9):
// horizontal blur + SSIM. Double-buffered tiles, named-barrier pipeline.
// Channels: blur(x), blur(y), blur(x^2+y^2), blur(xy) -> two packed f32x2.

#define IMG     512
#define NIMG    48
#define TX      64
#define TY      16
#define COLS    74              // TX + 10
#define VP      75              // V plane row stride in ulonglong2 elements
#define NT      320             // 10 warps: 5 producer + 5 consumer
#define NPROD   160
#define GXB     8
#define GYB     32
#define NTILES  (GXB*GYB*NIMG)  // 12288
#define NCTAS   444             // persistent grid: 3 CTAs/SM on 148 SMs
#define BUFQ    (TY*VP)         // 1200 ulonglong2 per buffer
#define SMEM_BYTES (2*BUFQ*16)  // 38400

#define W0f 0.00102838f
#define W1f 0.00759876f
#define W2f 0.03600077f
#define W3f 0.10936070f
#define W4f 0.21300554f
#define W5f 0.26601173f

__device__ float    g_partials[NCTAS];
__device__ unsigned g_sync = 0;

__device__ __forceinline__ uint64_t bc(float w) {
    unsigned u = __float_as_uint(w);
    return ((uint64_t)u << 32) | u;
}
__device__ __forceinline__ void f2fma(uint64_t& d, uint64_t a, uint64_t b) {
    asm("fma.rn.f32x2 %0,%1,%2,%0;" : "+l"(d) : "l"(a), "l"(b));
}
__device__ __forceinline__ uint64_t pack2(float lo, float hi) {
    uint64_t r; asm("mov.b64 %0,{%1,%2};" : "=l"(r) : "r"(__float_as_uint(lo)), "r"(__float_as_uint(hi)));
    return r;
}
__device__ __forceinline__ float lo32(uint64_t u) { return __uint_as_float((unsigned)u); }
__device__ __forceinline__ float hi32(uint64_t u) { return __uint_as_float((unsigned)(u >> 32)); }

#define BAR_SYNC(id)   asm volatile("bar.sync %0, %1;"   :: "r"(id), "r"(NT) : "memory")
#define BAR_ARRIVE(id) asm volatile("bar.arrive %0, %1;" :: "r"(id), "r"(NT) : "memory")
// barrier ids: FULL buffers = 1+p, EMPTY buffers = 3+p  (p in {0,1})

// Vertical accumulation body; RCHK adds per-row bounds predication.
template<bool RCHK>
__device__ __forceinline__ void vbody(const float* __restrict__ p1,
                                      const float* __restrict__ p2,
                                      int gy_first,
                                      uint64_t (&a01)[8], uint64_t (&asp)[8],
                                      const uint64_t (&Wb)[6])
{
    #pragma unroll
    for (int e = 0; e < 18; e++) {
        float x, y;
        if (RCHK) {
            bool ok = (unsigned)(gy_first + e) < (unsigned)IMG;
            x = ok ? __ldg(p1 + e * IMG) : 0.0f;
            y = ok ? __ldg(p2 + e * IMG) : 0.0f;
        } else {
            x = __ldg(p1 + e * IMG);
            y = __ldg(p2 + e * IMG);
        }
        uint64_t xy = pack2(x, y);
        uint64_t sp = pack2(fmaf(y, y, x * x), x * y);
        #pragma unroll
        for (int o = 0; o < 8; o++) {
            const int d = e - o;
            if (d >= 0 && d < 11) {
                const int wi = (d < 6) ? d : 10 - d;
                f2fma(a01[o], Wb[wi], xy);
                f2fma(asp[o], Wb[wi], sp);
            }
        }
    }
}

// Horizontal blur strip of LEN output cols + pointwise SSIM.
template<int LEN>
__device__ __forceinline__ float hstrip(const ulonglong2* __restrict__ B, int row, int cs,
                                        const uint64_t (&Wb)[6])
{
    const ulonglong2* p = B + row * VP + cs;
    uint64_t b01[LEN], bsp[LEN];
    #pragma unroll
    for (int o = 0; o < LEN; o++) { b01[o] = 0ull; bsp[o] = 0ull; }

    #pragma unroll
    for (int e = 0; e < LEN + 10; e++) {
        ulonglong2 f = p[e];                 // one LDS.128: both planes
        #pragma unroll
        for (int o = 0; o < LEN; o++) {
            const int d = e - o;
            if (d >= 0 && d < 11) {
                const int wi = (d < 6) ? d : 10 - d;
                f2fma(b01[o], Wb[wi], f.x);
                f2fma(bsp[o], Wb[wi], f.y);
            }
        }
    }

    const float C1 = 1e-4f, C2 = 9e-4f;
    float acc = 0.f;
    #pragma unroll
    for (int o = 0; o < LEN; o++) {
        float mu1 = lo32(b01[o]), mu2 = hi32(b01[o]);
        float Sb  = lo32(bsp[o]), Pb  = hi32(bsp[o]);
        float mu1sq = mu1 * mu1;
        float musum = fmaf(mu2, mu2, mu1sq);
        float mu12  = mu1 * mu2;
        float sg12  = Pb - mu12;
        float sgsum = Sb - musum;
        float num = fmaf(2.0f, mu12, C1) * fmaf(2.0f, sg12, C2);
        float den = (musum + C1) * (sgsum + C2);
        acc += __fdividef(num, den);
    }
    return acc;
}

__global__ __launch_bounds__(NT, 3)
void ssim_kernel(const float* __restrict__ img1,
                 const float* __restrict__ img2,
                 float* __restrict__ out)
{
    extern __shared__ ulonglong2 S[];   // two buffers of [TY][VP]
    const int tid = threadIdx.x;
    const bool producer = (tid < NPROD);

    const uint64_t Wb[6] = { bc(W0f), bc(W1f), bc(W2f), bc(W3f), bc(W4f), bc(W5f) };

    float acc = 0.f;
    int i = 0;
    for (int t = blockIdx.x; t < NTILES; t += NCTAS, i++) {
        const int p = i & 1;
        ulonglong2* buf = S + p * BUFQ;
        const int bx = t & (GXB - 1);
        const int by = (t >> 3) & (GYB - 1);
        const int bz = t >> 8;
        const int gx0 = bx * TX - 5;
        const int gy0 = by * TY - 5;

        if (producer) {
            if (i >= 2) BAR_SYNC(3 + p);          // wait buffer empty
            if (tid < COLS * 2) {
                const float* ib1 = img1 + (size_t)bz * IMG * IMG;
                const float* ib2 = img2 + (size_t)bz * IMG * IMG;
                int s = (tid >= COLS) ? 1 : 0;
                int c = tid - s * COLS;           // 0..73
                int gx = gx0 + c;
                int r0 = s * 8;

                uint64_t a01[8], asp[8];
                #pragma unroll
                for (int o = 0; o < 8; o++) { a01[o] = 0ull; asp[o] = 0ull; }

                const bool colsafe = (gx0 >= 0) & (gx0 + COLS - 1 < IMG);
                if (colsafe | ((unsigned)gx < (unsigned)IMG)) {
                    const int gy_first = gy0 + r0;
                    const float* p1 = ib1 + (size_t)gy_first * IMG + gx;
                    const float* p2 = ib2 + (size_t)gy_first * IMG + gx;
                    const bool rowsafe = (gy0 >= 0) & (gy0 + TY + 9 < IMG);
                    if (rowsafe) vbody<false>(p1, p2, gy_first, a01, asp, Wb);
                    else         vbody<true >(p1, p2, gy_first, a01, asp, Wb);
                }
                #pragma unroll
                for (int o = 0; o < 8; o++)
                    buf[(r0 + o) * VP + c] = make_ulonglong2(a01[o], asp[o]);
            }
            __threadfence_block();
            BAR_ARRIVE(1 + p);                    // buffer full
        } else {
            BAR_SYNC(1 + p);                      // wait buffer full
            const int ct  = tid - NPROD;
            const int row = ct & 15;
            const int g   = ct >> 4;              // 0..9, warp-uniform pairs
            if (g < 4) acc += hstrip<7>(buf, row, g * 7, Wb);
            else       acc += hstrip<6>(buf, row, 28 + (g - 4) * 6, Wb);
            __threadfence_block();
            BAR_ARRIVE(3 + p);                    // buffer empty
        }
    }

    // ---- block reduction (producers contribute 0) ----
    __syncthreads();
    #pragma unroll
    for (int off = 16; off > 0; off >>= 1)
        acc += __shfl_xor_sync(0xFFFFFFFFu, acc, off);

    __shared__ float warpsum[NT / 32];
    if ((tid & 31) == 0) warpsum[tid >> 5] = acc;
    __syncthreads();

    __shared__ bool is_last;
    if (tid == 0) {
        float s = 0.f;
        #pragma unroll
        for (int k = 0; k < NT / 32; k++) s += warpsum[k];
        g_partials[blockIdx.x] = s;
        __threadfence();
        unsigned prev = atomicAdd(&g_sync, 1u);
        is_last = (prev == NCTAS - 1);
    }
    __syncthreads();

    // ---- last CTA: deterministic final reduction ----
    if (is_last) {
        __threadfence();
        __shared__ double sd[NT];
        double s = (double)g_partials[tid];
        if (tid + NT < NCTAS) s += (double)g_partials[tid + NT];
        sd[tid] = s;
        __syncthreads();
        if (tid < 160) sd[tid] += sd[tid + 160];
        __syncthreads();
        if (tid < 80)  sd[tid] += sd[tid + 80];
        __syncthreads();
        if (tid < 40)  sd[tid] += sd[tid + 40];
        __syncthreads();
        if (tid < 20)  sd[tid] += sd[tid + 20];
        __syncthreads();
        if (tid < 10)  sd[tid] += sd[tid + 10];
        __syncthreads();
        if (tid == 0) {
            double tot = 0.0;
            #pragma unroll
            for (int k = 0; k < 10; k++) tot += sd[k];
            const double N = 16.0 * 3.0 * 512.0 * 512.0;
            out[0] = (float)(1.0 - tot / N);
            g_sync = 0;     // reset for next graph replay
        }
    }
}

extern "C" void kernel_launch(void* const* d_in, const int* in_sizes, int n_in,
                              void* d_out, int out_size)
{
    const float* img1 = (const float*)d_in[0];
    const float* img2 = (const float*)d_in[1];
    float* out = (float*)d_out;

    cudaFuncSetAttribute(ssim_kernel,
                         cudaFuncAttributeMaxDynamicSharedMemorySize, SMEM_BYTES);

    ssim_kernel<<<NCTAS, NT, SMEM_BYTES>>>(img1, img2, out);
}